// round 15
// baseline (speedup 1.0000x reference)
#include <cuda_runtime.h>

// CollisionLoss, f32x2 PACKED GRAM form (R6 structure x R11 core).
// pos [B=65536, N=24, 3] f32 -> scalar f32.
// Per batch, masked pairs (i<j, i>=1, skip (2,3)):
//   sq = |p_i-p_j|^2 ; if sq < 0.25: sum += exp(-4*sq); cnt++
// out = (cnt>0 ? sum/cnt : 0) + 1e-6
// Coords pre-scaled at staging by sqrt(4*log2 e): term = 2^(-s), test s < log2 e.
// Each thread = 2 batches (lo/hi f32x2 halves). Gram: s = (ni+nj) - 2<pi,pj>
// -> per 2 real pairs: ADD2 + 3 FMA2 (minimum fma work) + 2 MUFU + compare/
// select tail. Point layout per lane row: 24 x (x2,y2,z2,n2) u64 cells,
// row stride 97 u64 (odd -> conflict-free LDS.128 across lanes).

typedef unsigned long long u64;

#define THREADS 128
#define FLOATS_PER 72
#define PTS 24
#define ROW_U64 97                // 24*4 + 1 pad; odd stride -> conflict-free
#define BATCHES_PER_BLOCK 64
#define MAX_BLOCKS 1024

__device__ float g_psum[MAX_BLOCKS];
__device__ float g_pcnt[MAX_BLOCKS];
__device__ unsigned int g_ticket = 0;

__device__ __forceinline__ u64 f2_mul(u64 a, u64 b) {
    u64 d; asm("mul.rn.f32x2 %0, %1, %2;" : "=l"(d) : "l"(a), "l"(b)); return d;
}
__device__ __forceinline__ u64 f2_add(u64 a, u64 b) {
    u64 d; asm("add.rn.f32x2 %0, %1, %2;" : "=l"(d) : "l"(a), "l"(b)); return d;
}
__device__ __forceinline__ u64 f2_fma(u64 a, u64 b, u64 c) {
    u64 d; asm("fma.rn.f32x2 %0, %1, %2, %3;" : "=l"(d) : "l"(a), "l"(b), "l"(c)); return d;
}
__device__ __forceinline__ float nex2(float s) {   // 2^(-s); neg folds into MUFU src mod
    float e;
    asm("{\n\t.reg .f32 t;\n\tneg.f32 t, %1;\n\tex2.approx.f32 %0, t;\n\t}"
        : "=f"(e) : "f"(s));
    return e;
}

#define NEG2_F32X2 0xC0000000C0000000ULL   // (-2.0f, -2.0f)

// One packed pair (2 real pairs), Gram form.
#define PAIRG(qx_, qy_, qz_, n2_, jx_, jy_, jz_, jn_)                 \
    do {                                                              \
        u64 s2 = f2_add((n2_), (jn_));        /* ni + nj */           \
        s2 = f2_fma((qx_), (jx_), s2);        /* -2<pi,pj> */         \
        s2 = f2_fma((qy_), (jy_), s2);                                \
        s2 = f2_fma((qz_), (jz_), s2);        /* scaled sq */         \
        float sl, sh;                                                 \
        asm("mov.b64 {%0, %1}, %2;" : "=f"(sl), "=f"(sh) : "l"(s2));  \
        float el = nex2(sl);                                          \
        float eh = nex2(sh);                                          \
        float wl = (sl < 1.44269504f) ? 1.0f : 0.0f;                  \
        float wh = (sh < 1.44269504f) ? 1.0f : 0.0f;                  \
        u64 w2, e2;                                                   \
        asm("mov.b64 %0, {%1, %2};" : "=l"(w2) : "f"(wl), "f"(wh));   \
        asm("mov.b64 %0, {%1, %2};" : "=l"(e2) : "f"(el), "f"(eh));   \
        sum2 = f2_fma(e2, w2, sum2);                                  \
        cnt2 = f2_add(cnt2, w2);                                      \
    } while (0)

// i in [I0, I1] preloaded (q2 = -2*p packed, n2); j streamed over (I0, 23].
// Only i<j pairs; (2,3) excluded at compile time.
template <int I0, int I1>
__device__ __forceinline__ void tri_gram(const u64* __restrict__ row,
                                         u64& sum2, u64& cnt2) {
    const int NI = I1 - I0 + 1;
    u64 qx[NI], qy[NI], qz[NI], n2[NI];
    #pragma unroll
    for (int k = 0; k < NI; k++) {
        const int base = (I0 + k) * 4;
        qx[k] = f2_mul(row[base + 0], NEG2_F32X2);
        qy[k] = f2_mul(row[base + 1], NEG2_F32X2);
        qz[k] = f2_mul(row[base + 2], NEG2_F32X2);
        n2[k] = row[base + 3];
    }
    #pragma unroll
    for (int j = I0 + 1; j <= 23; j++) {
        const int jb = j * 4;
        u64 jx = row[jb + 0];                  // adjacent u64s -> 2x LDS.128
        u64 jy = row[jb + 1];
        u64 jz = row[jb + 2];
        u64 jn = row[jb + 3];
        #pragma unroll
        for (int k = 0; k < NI; k++) {
            const int i = I0 + k;
            if (i >= j) continue;              // compile-time
            if (i == 2 && j == 3) continue;    // excluded pair, compile-time
            PAIRG(qx[k], qy[k], qz[k], n2[k], jx, jy, jz, jn);
        }
    }
}

__global__ __launch_bounds__(THREADS, 8)
void collision_pg_kernel(const float* __restrict__ pos, float* __restrict__ out, int B) {
    __shared__ u64 smu[32 * ROW_U64];           // 32 lanes x (24 pts x 4 cells + pad)
    __shared__ float wsum[THREADS / 32];
    __shared__ float wcnt[THREADS / 32];
    __shared__ bool  amLast;
    float* smf = reinterpret_cast<float*>(smu);

    const int tid   = threadIdx.x;
    const int role  = tid >> 5;
    const int lane  = tid & 31;
    const int bbase = blockIdx.x * BATCHES_PER_BLOCK;
    const int nvalid = min(BATCHES_PER_BLOCK, B - bbase);

    // ---- Stage A: coalesced float4 gmem -> packed (lo,hi) smem cells ----
    // Batch bl -> lane = bl&31, half = bl>>5. Point p comp c lives in u64 cell
    // lane*97 + p*4 + c, float slot [cell*2 + half].
    {
        const float SCALE = 2.4022448929611436f;   // sqrt(4 * log2 e)
        const float4* src4 = reinterpret_cast<const float4*>(pos + (size_t)bbase * FLOATS_PER);
        const int n4 = nvalid * 18;
        for (int q = tid; q < BATCHES_PER_BLOCK * 18; q += THREADS) {
            float4 v = make_float4(0.f, 0.f, 0.f, 0.f);
            if (q < n4) v = src4[q];
            int bl = q / 18;
            int g  = (q - bl * 18) << 2;           // first float index in batch
            int ln = bl & 31, hf = bl >> 5;
            float vals[4] = {v.x, v.y, v.z, v.w};
            #pragma unroll
            for (int t = 0; t < 4; t++) {
                int wf = g + t;
                int p  = wf / 3;
                int c  = wf - p * 3;
                smf[(ln * ROW_U64 + p * 4 + c) * 2 + hf] = vals[t] * SCALE;
            }
        }
    }
    __syncthreads();

    // ---- Stage B: per-point norms into the 4th cell (scalar per half) ----
    {
        for (int idx = tid; idx < BATCHES_PER_BLOCK * PTS; idx += THREADS) {
            int bl = idx / PTS;
            int p  = idx - bl * PTS;
            int ln = bl & 31, hf = bl >> 5;
            int base = ln * ROW_U64 + p * 4;
            float x = smf[(base + 0) * 2 + hf];
            float y = smf[(base + 1) * 2 + hf];
            float z = smf[(base + 2) * 2 + hf];
            float n = x * x;
            n = fmaf(y, y, n);
            n = fmaf(z, z, n);
            smf[(base + 3) * 2 + hf] = n;
        }
    }
    __syncthreads();

    u64 sum2 = 0, cnt2 = 0;                      // packed (lo,hi) accumulators

    {
        const u64* row = &smu[lane * ROW_U64];
        // Roles (packed pairs): 0:<1,3> 62 | 1:<4,7> 70 | 2:<8,11>+<19,22> 64 | 3:<12,15>+<16,18> 56
        if (role == 0) {
            tri_gram<1, 3>(row, sum2, cnt2);
        } else if (role == 1) {
            tri_gram<4, 7>(row, sum2, cnt2);
        } else if (role == 2) {
            tri_gram<8, 11>(row, sum2, cnt2);
            tri_gram<19, 22>(row, sum2, cnt2);
        } else {
            tri_gram<12, 15>(row, sum2, cnt2);
            tri_gram<16, 18>(row, sum2, cnt2);
        }
    }

    // Unpack + validity gating (zero-padded halves can't contribute).
    float sum_lo, sum_hi, cnt_lo, cnt_hi;
    asm("mov.b64 {%0, %1}, %2;" : "=f"(sum_lo), "=f"(sum_hi) : "l"(sum2));
    asm("mov.b64 {%0, %1}, %2;" : "=f"(cnt_lo), "=f"(cnt_hi) : "l"(cnt2));
    const bool vlo = (bbase + lane) < B;
    const bool vhi = (bbase + 32 + lane) < B;
    float lsum = (vlo ? sum_lo : 0.0f) + (vhi ? sum_hi : 0.0f);
    float lcnt = (vlo ? cnt_lo : 0.0f) + (vhi ? cnt_hi : 0.0f);

    // ---- Block reduce ----
    #pragma unroll
    for (int o = 16; o > 0; o >>= 1) {
        lsum += __shfl_down_sync(0xffffffffu, lsum, o);
        lcnt += __shfl_down_sync(0xffffffffu, lcnt, o);
    }
    if (lane == 0) { wsum[role] = lsum; wcnt[role] = lcnt; }
    __syncthreads();
    if (tid == 0) {
        float s = 0.0f, c = 0.0f;
        #pragma unroll
        for (int w = 0; w < THREADS / 32; w++) { s += wsum[w]; c += wcnt[w]; }
        g_psum[blockIdx.x] = s;
        g_pcnt[blockIdx.x] = c;
        __threadfence();
        unsigned int t = atomicAdd(&g_ticket, 1u);
        amLast = (t == gridDim.x - 1);
    }
    __syncthreads();

    // ---- Last block finalizes ----
    if (amLast) {
        const int nb = gridDim.x;
        float s = 0.0f, c = 0.0f;
        for (int i = tid; i < nb; i += THREADS) {
            s += g_psum[i];
            c += g_pcnt[i];
        }
        #pragma unroll
        for (int o = 16; o > 0; o >>= 1) {
            s += __shfl_down_sync(0xffffffffu, s, o);
            c += __shfl_down_sync(0xffffffffu, c, o);
        }
        if (lane == 0) { wsum[role] = s; wcnt[role] = c; }
        __syncthreads();
        if (tid == 0) {
            float ts = 0.0f, tc = 0.0f;
            #pragma unroll
            for (int w = 0; w < THREADS / 32; w++) { ts += wsum[w]; tc += wcnt[w]; }
            float total = (tc > 0.0f) ? (ts / fmaxf(tc, 1.0f)) : 0.0f;
            out[0] = total + 1e-6f;
            g_ticket = 0;   // reset for next graph replay
        }
    }
}

extern "C" void kernel_launch(void* const* d_in, const int* in_sizes, int n_in,
                              void* d_out, int out_size) {
    const float* pos = (const float*)d_in[0];
    const int B = in_sizes[0] / FLOATS_PER;
    int nblocks = (B + BATCHES_PER_BLOCK - 1) / BATCHES_PER_BLOCK;   // 1024 for B=65536
    if (nblocks > MAX_BLOCKS) nblocks = MAX_BLOCKS;
    collision_pg_kernel<<<nblocks, THREADS>>>(pos, (float*)d_out, B);
}

// round 16
// speedup vs baseline: 1.0089x; 1.0089x over previous
#include <cuda_runtime.h>

// CollisionLoss, f32x2 packed Gram v2: sign-folded norms + aligned LDS.128.
// pos [B=65536, N=24, 3] f32 -> scalar f32.
// Per batch, masked pairs (i<j, i>=1, skip (2,3)):
//   sq = |p_i-p_j|^2 ; if sq < 0.25: sum += exp(-4*sq); cnt++
// out = (cnt>0 ? sum/cnt : 0) + 1e-6
// Staging stores a = c*p with c^2 = 8*log2(e), and the 4th cell nn = -|a|^2/2.
// Then d = nn_i + nn_j + <a_i,a_j> = -4*log2(e)*sq, so:
//   term = 2^d  (raw EX2, no negate), collision test d > -log2(e).
// Core per 2 real pairs: ADD2 + 3*FMA2; i-preload is pure LDS (no transform).
// Row stride 98 u64 = 784B = 49*16 -> every (x2,y2)/(z2,n2) cell pair is
// 16B-aligned => 2x LDS.128 per j; phase banks 4*lane mod 32 distinct =>
// conflict-free. (R15's stride 97 broke alignment -> 4x LDS.64, L1 37%.)

typedef unsigned long long u64;

#define THREADS 128
#define FLOATS_PER 72
#define PTS 24
#define ROW_U64 98                // 24*4 + 2 pad; 784B row -> 16B-aligned cells
#define BATCHES_PER_BLOCK 64
#define MAX_BLOCKS 1024

__device__ float g_psum[MAX_BLOCKS];
__device__ float g_pcnt[MAX_BLOCKS];
__device__ unsigned int g_ticket = 0;

__device__ __forceinline__ u64 f2_add(u64 a, u64 b) {
    u64 d; asm("add.rn.f32x2 %0, %1, %2;" : "=l"(d) : "l"(a), "l"(b)); return d;
}
__device__ __forceinline__ u64 f2_fma(u64 a, u64 b, u64 c) {
    u64 d; asm("fma.rn.f32x2 %0, %1, %2, %3;" : "=l"(d) : "l"(a), "l"(b), "l"(c)); return d;
}
__device__ __forceinline__ float ex2(float d) {    // 2^d, single MUFU
    float e; asm("ex2.approx.f32 %0, %1;" : "=f"(e) : "f"(d)); return e;
}

// One packed pair (2 real pairs). d = nn_i + nn_j + <a_i, a_j> (= -4*log2e*sq).
#define PAIRG(ax_, ay_, az_, nn_, jx_, jy_, jz_, jn_)                 \
    do {                                                              \
        u64 d2 = f2_add((nn_), (jn_));                                \
        d2 = f2_fma((ax_), (jx_), d2);                                \
        d2 = f2_fma((ay_), (jy_), d2);                                \
        d2 = f2_fma((az_), (jz_), d2);                                \
        float dl, dh;                                                 \
        asm("mov.b64 {%0, %1}, %2;" : "=f"(dl), "=f"(dh) : "l"(d2));  \
        float el = ex2(dl);                                           \
        float eh = ex2(dh);                                           \
        float wl = (dl > -1.44269504f) ? 1.0f : 0.0f;                 \
        float wh = (dh > -1.44269504f) ? 1.0f : 0.0f;                 \
        sum_lo = fmaf(el, wl, sum_lo);  cnt_lo += wl;                 \
        sum_hi = fmaf(eh, wh, sum_hi);  cnt_hi += wh;                 \
    } while (0)

// i in [I0, I1] preloaded raw (no transform); j streamed over (I0, 23].
// Only i<j pairs; (2,3) excluded at compile time.
template <int I0, int I1>
__device__ __forceinline__ void tri_gram(const u64* __restrict__ row,
                                         float& sum_lo, float& sum_hi,
                                         float& cnt_lo, float& cnt_hi) {
    const int NI = I1 - I0 + 1;
    u64 ax[NI], ay[NI], az[NI], nn[NI];
    #pragma unroll
    for (int k = 0; k < NI; k++) {
        const int base = (I0 + k) * 4;
        ax[k] = row[base + 0];
        ay[k] = row[base + 1];
        az[k] = row[base + 2];
        nn[k] = row[base + 3];
    }
    #pragma unroll
    for (int j = I0 + 1; j <= 23; j++) {
        const int jb = j * 4;
        u64 jx = row[jb + 0];                  // 16B-aligned -> LDS.128
        u64 jy = row[jb + 1];
        u64 jz = row[jb + 2];                  // second LDS.128
        u64 jn = row[jb + 3];
        #pragma unroll
        for (int k = 0; k < NI; k++) {
            const int i = I0 + k;
            if (i >= j) continue;              // compile-time
            if (i == 2 && j == 3) continue;    // excluded pair, compile-time
            PAIRG(ax[k], ay[k], az[k], nn[k], jx, jy, jz, jn);
        }
    }
}

__global__ __launch_bounds__(THREADS, 8)
void collision_pg2_kernel(const float* __restrict__ pos, float* __restrict__ out, int B) {
    __shared__ u64 smu[32 * ROW_U64];           // 32 lanes x (24 pts x 4 cells + pad)
    __shared__ float wsum[THREADS / 32];
    __shared__ float wcnt[THREADS / 32];
    __shared__ bool  amLast;
    float* smf = reinterpret_cast<float*>(smu);

    const int tid   = threadIdx.x;
    const int role  = tid >> 5;
    const int lane  = tid & 31;
    const int bbase = blockIdx.x * BATCHES_PER_BLOCK;
    const int nvalid = min(BATCHES_PER_BLOCK, B - bbase);

    // ---- Stage A: coalesced float4 gmem -> packed (lo,hi) smem cells ----
    // a = SCALE2 * p, SCALE2 = sqrt(8*log2 e). Batch bl -> lane bl&31, half bl>>5.
    {
        const float SCALE2 = 3.3972871923588166f;  // sqrt(8 * log2 e)
        const float4* src4 = reinterpret_cast<const float4*>(pos + (size_t)bbase * FLOATS_PER);
        const int n4 = nvalid * 18;
        for (int q = tid; q < BATCHES_PER_BLOCK * 18; q += THREADS) {
            float4 v = make_float4(0.f, 0.f, 0.f, 0.f);
            if (q < n4) v = src4[q];
            int bl = q / 18;
            int g  = (q - bl * 18) << 2;           // first float index in batch
            int ln = bl & 31, hf = bl >> 5;
            float vals[4] = {v.x, v.y, v.z, v.w};
            #pragma unroll
            for (int t = 0; t < 4; t++) {
                int wf = g + t;
                int p  = wf / 3;
                int c  = wf - p * 3;
                smf[(ln * ROW_U64 + p * 4 + c) * 2 + hf] = vals[t] * SCALE2;
            }
        }
    }
    __syncthreads();

    // ---- Stage B: nn = -|a|^2 / 2 into the 4th cell ----
    {
        for (int idx = tid; idx < BATCHES_PER_BLOCK * PTS; idx += THREADS) {
            int bl = idx / PTS;
            int p  = idx - bl * PTS;
            int ln = bl & 31, hf = bl >> 5;
            int base = ln * ROW_U64 + p * 4;
            float x = smf[(base + 0) * 2 + hf];
            float y = smf[(base + 1) * 2 + hf];
            float z = smf[(base + 2) * 2 + hf];
            float m = x * x;
            m = fmaf(y, y, m);
            m = fmaf(z, z, m);
            smf[(base + 3) * 2 + hf] = -0.5f * m;
        }
    }
    __syncthreads();

    float sum_lo = 0.0f, sum_hi = 0.0f, cnt_lo = 0.0f, cnt_hi = 0.0f;

    {
        const u64* row = &smu[lane * ROW_U64];
        // Roles (real pairs, lo+hi counted once): 0:<1,3> 62 | 1:<4,7> 70 |
        // 2:<8,11>+<19,22> 64 | 3:<12,15>+<16,18> 56   (total 252)
        if (role == 0) {
            tri_gram<1, 3>(row, sum_lo, sum_hi, cnt_lo, cnt_hi);
        } else if (role == 1) {
            tri_gram<4, 7>(row, sum_lo, sum_hi, cnt_lo, cnt_hi);
        } else if (role == 2) {
            tri_gram<8, 11>(row, sum_lo, sum_hi, cnt_lo, cnt_hi);
            tri_gram<19, 22>(row, sum_lo, sum_hi, cnt_lo, cnt_hi);
        } else {
            tri_gram<12, 15>(row, sum_lo, sum_hi, cnt_lo, cnt_hi);
            tri_gram<16, 18>(row, sum_lo, sum_hi, cnt_lo, cnt_hi);
        }
    }

    // Validity gating (zero-padded halves can't contribute).
    const bool vlo = (bbase + lane) < B;
    const bool vhi = (bbase + 32 + lane) < B;
    float lsum = (vlo ? sum_lo : 0.0f) + (vhi ? sum_hi : 0.0f);
    float lcnt = (vlo ? cnt_lo : 0.0f) + (vhi ? cnt_hi : 0.0f);

    // ---- Block reduce ----
    #pragma unroll
    for (int o = 16; o > 0; o >>= 1) {
        lsum += __shfl_down_sync(0xffffffffu, lsum, o);
        lcnt += __shfl_down_sync(0xffffffffu, lcnt, o);
    }
    if (lane == 0) { wsum[role] = lsum; wcnt[role] = lcnt; }
    __syncthreads();
    if (tid == 0) {
        float s = 0.0f, c = 0.0f;
        #pragma unroll
        for (int w = 0; w < THREADS / 32; w++) { s += wsum[w]; c += wcnt[w]; }
        g_psum[blockIdx.x] = s;
        g_pcnt[blockIdx.x] = c;
        __threadfence();
        unsigned int t = atomicAdd(&g_ticket, 1u);
        amLast = (t == gridDim.x - 1);
    }
    __syncthreads();

    // ---- Last block finalizes ----
    if (amLast) {
        const int nb = gridDim.x;
        float s = 0.0f, c = 0.0f;
        for (int i = tid; i < nb; i += THREADS) {
            s += g_psum[i];
            c += g_pcnt[i];
        }
        #pragma unroll
        for (int o = 16; o > 0; o >>= 1) {
            s += __shfl_down_sync(0xffffffffu, s, o);
            c += __shfl_down_sync(0xffffffffu, c, o);
        }
        if (lane == 0) { wsum[role] = s; wcnt[role] = c; }
        __syncthreads();
        if (tid == 0) {
            float ts = 0.0f, tc = 0.0f;
            #pragma unroll
            for (int w = 0; w < THREADS / 32; w++) { ts += wsum[w]; tc += wcnt[w]; }
            float total = (tc > 0.0f) ? (ts / fmaxf(tc, 1.0f)) : 0.0f;
            out[0] = total + 1e-6f;
            g_ticket = 0;   // reset for next graph replay
        }
    }
}

extern "C" void kernel_launch(void* const* d_in, const int* in_sizes, int n_in,
                              void* d_out, int out_size) {
    const float* pos = (const float*)d_in[0];
    const int B = in_sizes[0] / FLOATS_PER;
    int nblocks = (B + BATCHES_PER_BLOCK - 1) / BATCHES_PER_BLOCK;   // 1024 for B=65536
    if (nblocks > MAX_BLOCKS) nblocks = MAX_BLOCKS;
    collision_pg2_kernel<<<nblocks, THREADS>>>(pos, (float*)d_out, B);
}

// round 17
// speedup vs baseline: 1.1931x; 1.1825x over previous
#include <cuda_runtime.h>

// CollisionLoss = R6 champion (19.2us) + exact role balancing (63/63/63/63).
// pos [B=65536, N=24, 3] f32 -> scalar f32.
// Per batch, masked pairs (i<j, i>=1, skip (2,3)):
//   sq = |p_i-p_j|^2 ; if sq < 0.25: sum += exp(-4*sq); cnt++
// out = (cnt>0 ? sum/cnt : 0) + 1e-6
// Coords pre-scaled at staging by sqrt(4*log2 e): term = 2^(-s), test s < log2 e.
// Each thread = 2 batches (lo/hi f32x2 halves); distance form (24B/j LDS —
// gram-with-norms costs more smem traffic and lost in R11/12/15/16).
// ONLY change vs R6: roles were 62/70/64/56 packed pairs (block waits on 70);
// now 63/63/63/63 via j-range splits. Everything else byte-identical.

typedef unsigned long long u64;

#define THREADS 128
#define FLOATS_PER 72
#define ROW_F2 73                 // float2 cells per lane row (72 + 1 pad)
#define BATCHES_PER_BLOCK 64
#define MAX_BLOCKS 1024

__device__ float g_psum[MAX_BLOCKS];
__device__ float g_pcnt[MAX_BLOCKS];
__device__ unsigned int g_ticket = 0;

__device__ __forceinline__ u64 f2_mul(u64 a, u64 b) {
    u64 d; asm("mul.rn.f32x2 %0, %1, %2;" : "=l"(d) : "l"(a), "l"(b)); return d;
}
__device__ __forceinline__ u64 f2_fma(u64 a, u64 b, u64 c) {
    u64 d; asm("fma.rn.f32x2 %0, %1, %2, %3;" : "=l"(d) : "l"(a), "l"(b), "l"(c)); return d;
}
__device__ __forceinline__ float nex2(float s) {   // 2^(-s), neg folds into MUFU src mod
    float e;
    asm("{\n\t.reg .f32 t;\n\tneg.f32 t, %1;\n\tex2.approx.f32 %0, t;\n\t}"
        : "=f"(e) : "f"(s));
    return e;
}

#define NEG1_F32X2 0xBF800000BF800000ULL

// One packed pair: 2 real pairs (lo batch + hi batch). FSEL-based tail.
#define PAIR2(ix_, iy_, iz_, jx_, jy_, jz_)                           \
    do {                                                              \
        u64 d0 = f2_fma((jx_), NEG1, (ix_));   /* i - j */            \
        u64 d1 = f2_fma((jy_), NEG1, (iy_));                          \
        u64 d2 = f2_fma((jz_), NEG1, (iz_));                          \
        u64 s2 = f2_mul(d0, d0);                                      \
        s2 = f2_fma(d1, d1, s2);                                      \
        s2 = f2_fma(d2, d2, s2);           /* scaled sq >= 0 */       \
        float sl, sh;                                                 \
        asm("mov.b64 {%0, %1}, %2;" : "=f"(sl), "=f"(sh) : "l"(s2));  \
        float el = nex2(sl);                                          \
        float eh = nex2(sh);                                          \
        float wl = (sl < 1.44269504f) ? 1.0f : 0.0f;                  \
        float wh = (sh < 1.44269504f) ? 1.0f : 0.0f;                  \
        sum_lo = fmaf(el, wl, sum_lo);  cnt_lo += wl;                 \
        sum_hi = fmaf(eh, wh, sum_hi);  cnt_hi += wh;                 \
    } while (0)

// i in [I0, I1] preloaded packed; j streamed over [JLO, JHI]; only i<j pairs;
// (2,3) excluded at compile time.
template <int I0, int I1, int JLO, int JHI>
__device__ __forceinline__ void tri_stream(const u64* __restrict__ row, u64 NEG1,
                                           float& sum_lo, float& sum_hi,
                                           float& cnt_lo, float& cnt_hi) {
    const int NI = I1 - I0 + 1;
    u64 ix[NI], iy[NI], iz[NI];
    #pragma unroll
    for (int k = 0; k < NI; k++) {
        ix[k] = row[(I0 + k) * 3 + 0];
        iy[k] = row[(I0 + k) * 3 + 1];
        iz[k] = row[(I0 + k) * 3 + 2];
    }
    #pragma unroll
    for (int j = JLO; j <= JHI; j++) {
        u64 jx = row[j * 3 + 0];
        u64 jy = row[j * 3 + 1];
        u64 jz = row[j * 3 + 2];
        #pragma unroll
        for (int k = 0; k < NI; k++) {
            const int i = I0 + k;
            if (i >= j) continue;             // compile-time
            if (i == 2 && j == 3) continue;   // excluded pair, compile-time
            PAIR2(ix[k], iy[k], iz[k], jx, jy, jz);
        }
    }
}

__global__ __launch_bounds__(THREADS, 8)
void collision_bal_kernel(const float* __restrict__ pos, float* __restrict__ out, int B) {
    __shared__ float smf[32 * ROW_F2 * 2];      // 32 lanes x 73 float2 cells
    __shared__ float wsum[THREADS / 32];
    __shared__ float wcnt[THREADS / 32];
    __shared__ bool  amLast;

    const int tid   = threadIdx.x;
    const int role  = tid >> 5;
    const int lane  = tid & 31;
    const int bbase = blockIdx.x * BATCHES_PER_BLOCK;
    const int nvalid = min(BATCHES_PER_BLOCK, B - bbase);

    // ---- Stage: coalesced float4 gmem -> interleaved (lo,hi) float2 smem ----
    {
        const float SCALE = 2.4022448929611436f;   // sqrt(4 * log2 e)
        const float4* src4 = reinterpret_cast<const float4*>(pos + (size_t)bbase * FLOATS_PER);
        const int n4 = nvalid * 18;
        for (int q = tid; q < BATCHES_PER_BLOCK * 18; q += THREADS) {
            float4 v = make_float4(0.f, 0.f, 0.f, 0.f);
            if (q < n4) v = src4[q];
            int bl = q / 18;
            int w4 = q - bl * 18;
            int ln = bl & 31, hf = bl >> 5;
            float* d = &smf[((ln * ROW_F2 + (w4 << 2)) << 1) + hf];
            d[0] = v.x * SCALE; d[2] = v.y * SCALE;
            d[4] = v.z * SCALE; d[6] = v.w * SCALE;
        }
    }
    __syncthreads();

    const u64 NEG1 = NEG1_F32X2;
    float sum_lo = 0.0f, sum_hi = 0.0f, cnt_lo = 0.0f, cnt_hi = 0.0f;

    {
        const u64* row = reinterpret_cast<const u64*>(&smf[lane * ROW_F2 * 2]);
        // Balanced roles, 63 packed pairs each (252 total, (2,3) excluded once):
        if (role == 0) {
            tri_stream<1, 3, 2, 23>(row, NEG1, sum_lo, sum_hi, cnt_lo, cnt_hi);   // 62
            tri_stream<4, 4, 5, 5>(row, NEG1, sum_lo, sum_hi, cnt_lo, cnt_hi);    // +1 (4,5)
        } else if (role == 1) {
            tri_stream<4, 4, 12, 23>(row, NEG1, sum_lo, sum_hi, cnt_lo, cnt_hi);  // 12
            tri_stream<5, 7, 6, 23>(row, NEG1, sum_lo, sum_hi, cnt_lo, cnt_hi);   // 51
        } else if (role == 2) {
            tri_stream<8, 11, 9, 23>(row, NEG1, sum_lo, sum_hi, cnt_lo, cnt_hi);  // 54
            tri_stream<19, 19, 21, 23>(row, NEG1, sum_lo, sum_hi, cnt_lo, cnt_hi);// 3 (19,21..23)
            tri_stream<20, 22, 21, 23>(row, NEG1, sum_lo, sum_hi, cnt_lo, cnt_hi);// 6
        } else {
            tri_stream<12, 15, 13, 23>(row, NEG1, sum_lo, sum_hi, cnt_lo, cnt_hi);// 38
            tri_stream<16, 18, 17, 23>(row, NEG1, sum_lo, sum_hi, cnt_lo, cnt_hi);// 18
            tri_stream<4, 4, 6, 11>(row, NEG1, sum_lo, sum_hi, cnt_lo, cnt_hi);   // 6 (4,6..11)
            tri_stream<19, 19, 20, 20>(row, NEG1, sum_lo, sum_hi, cnt_lo, cnt_hi);// +1 (19,20)
        }
    }

    // Validity gating (zero-padded halves can't contribute).
    const bool vlo = (bbase + lane) < B;
    const bool vhi = (bbase + 32 + lane) < B;
    float lsum = (vlo ? sum_lo : 0.0f) + (vhi ? sum_hi : 0.0f);
    float lcnt = (vlo ? cnt_lo : 0.0f) + (vhi ? cnt_hi : 0.0f);

    // ---- Block reduce ----
    #pragma unroll
    for (int o = 16; o > 0; o >>= 1) {
        lsum += __shfl_down_sync(0xffffffffu, lsum, o);
        lcnt += __shfl_down_sync(0xffffffffu, lcnt, o);
    }
    if (lane == 0) { wsum[role] = lsum; wcnt[role] = lcnt; }
    __syncthreads();
    if (tid == 0) {
        float s = 0.0f, c = 0.0f;
        #pragma unroll
        for (int w = 0; w < THREADS / 32; w++) { s += wsum[w]; c += wcnt[w]; }
        g_psum[blockIdx.x] = s;
        g_pcnt[blockIdx.x] = c;
        __threadfence();
        unsigned int t = atomicAdd(&g_ticket, 1u);
        amLast = (t == gridDim.x - 1);
    }
    __syncthreads();

    // ---- Last block finalizes ----
    if (amLast) {
        const int nb = gridDim.x;
        float s = 0.0f, c = 0.0f;
        for (int i = tid; i < nb; i += THREADS) {
            s += g_psum[i];
            c += g_pcnt[i];
        }
        #pragma unroll
        for (int o = 16; o > 0; o >>= 1) {
            s += __shfl_down_sync(0xffffffffu, s, o);
            c += __shfl_down_sync(0xffffffffu, c, o);
        }
        if (lane == 0) { wsum[role] = s; wcnt[role] = c; }
        __syncthreads();
        if (tid == 0) {
            float ts = 0.0f, tc = 0.0f;
            #pragma unroll
            for (int w = 0; w < THREADS / 32; w++) { ts += wsum[w]; tc += wcnt[w]; }
            float total = (tc > 0.0f) ? (ts / fmaxf(tc, 1.0f)) : 0.0f;
            out[0] = total + 1e-6f;
            g_ticket = 0;   // reset for next graph replay
        }
    }
}

extern "C" void kernel_launch(void* const* d_in, const int* in_sizes, int n_in,
                              void* d_out, int out_size) {
    const float* pos = (const float*)d_in[0];
    const int B = in_sizes[0] / FLOATS_PER;
    int nblocks = (B + BATCHES_PER_BLOCK - 1) / BATCHES_PER_BLOCK;   // 1024 for B=65536
    if (nblocks > MAX_BLOCKS) nblocks = MAX_BLOCKS;
    collision_bal_kernel<<<nblocks, THREADS>>>(pos, (float*)d_out, B);
}